// round 1
// baseline (speedup 1.0000x reference)
#include <cuda_runtime.h>
#include <cstdint>

// Flash-attention forward with the OmniAttention mixed mask, tf32 mma.sync.
// Tiles: Q_TILE=64 (16 rows per warp), KV_TILE=64, D=64. 4 warps / CTA.
// Grid: (S/64, B*H).

#define STRIDE 68  // smem row stride in words (4*row+col distinct banks)

__device__ __forceinline__ uint32_t f2tf(float x) {
    uint32_t r;
    asm("cvt.rna.tf32.f32 %0, %1;" : "=r"(r) : "f"(x));
    return r;
}

__device__ __forceinline__ void mma8(float* c, const uint32_t* a, uint32_t b0, uint32_t b1) {
    asm volatile(
        "mma.sync.aligned.m16n8k8.row.col.f32.tf32.tf32.f32 "
        "{%0,%1,%2,%3}, {%4,%5,%6,%7}, {%8,%9}, {%0,%1,%2,%3};\n"
        : "+f"(c[0]), "+f"(c[1]), "+f"(c[2]), "+f"(c[3])
        : "r"(a[0]), "r"(a[1]), "r"(a[2]), "r"(a[3]), "r"(b0), "r"(b1));
}

__global__ void __launch_bounds__(128)
omni_attn_kernel(const float* __restrict__ gq, const float* __restrict__ gk,
                 const float* __restrict__ gv,
                 const int* __restrict__ gpad, const int* __restrict__ gfs,
                 const int* __restrict__ gfe,
                 const int* __restrict__ p_bt2i, const int* __restrict__ p_blm,
                 float* __restrict__ gout, int H, int S)
{
    extern __shared__ float smem[];
    float* sK = smem;                    // 64 x STRIDE
    float* sV = sK + 64 * STRIDE;        // 64 x STRIDE
    float* sP = sV + 64 * STRIDE;        // 64 x STRIDE (Q staging, then P per warp)
    int*   sPad = (int*)(sP + 64 * STRIDE);

    const int tid  = threadIdx.x;
    const int warp = tid >> 5;
    const int lane = tid & 31;
    const int g = lane >> 2;   // group 0..7
    const int t = lane & 3;    // thread-in-group 0..3

    const int q0 = blockIdx.x * 64;
    const int bh = blockIdx.y;
    const int b  = bh / H;

    const int bt2i = p_bt2i[0];
    const int blm  = p_blm[0];
    const int mode = (b < bt2i) ? 0 : ((b < bt2i + blm) ? 1 : 2);

    const size_t base = (size_t)bh * S * 64;

    // ---- stage Q tile into sP (tf32-rounded) ----
    {
        const float4* src = (const float4*)(gq + base + (size_t)q0 * 64);
        #pragma unroll
        for (int i = tid; i < 1024; i += 128) {
            float4 x = src[i];
            float4 y;
            y.x = __uint_as_float(f2tf(x.x));
            y.y = __uint_as_float(f2tf(x.y));
            y.z = __uint_as_float(f2tf(x.z));
            y.w = __uint_as_float(f2tf(x.w));
            *(float4*)(sP + (i >> 4) * STRIDE + ((i & 15) << 2)) = y;
        }
    }
    __syncthreads();

    // ---- Q fragments live in registers for the whole kernel ----
    uint32_t qa[8][4];
    {
        const int r0 = warp * 16 + g;
        #pragma unroll
        for (int kt = 0; kt < 8; kt++) {
            qa[kt][0] = __float_as_uint(sP[r0       * STRIDE + kt * 8 + t]);
            qa[kt][1] = __float_as_uint(sP[(r0 + 8) * STRIDE + kt * 8 + t]);
            qa[kt][2] = __float_as_uint(sP[r0       * STRIDE + kt * 8 + t + 4]);
            qa[kt][3] = __float_as_uint(sP[(r0 + 8) * STRIDE + kt * 8 + t + 4]);
        }
    }

    const int qr0 = q0 + warp * 16 + g;   // global q row (lane's row 0)
    const int qr1 = qr0 + 8;              // global q row (lane's row 1)
    int fs0 = 0, fe0 = 0, fs1 = 0, fe1 = 0;
    if (mode == 0) {
        fs0 = gfs[qr0]; fe0 = gfe[qr0];
        fs1 = gfs[qr1]; fe1 = gfe[qr1];
    }

    float o[8][4];
    #pragma unroll
    for (int n = 0; n < 8; n++) { o[n][0] = o[n][1] = o[n][2] = o[n][3] = 0.f; }
    float m0 = -1e30f, m1 = -1e30f, l0 = 0.f, l1 = 0.f;

    const int pr0 = warp * 16 + g;        // this lane's row in sP
    const float scale = 0.125f;           // 1/sqrt(64)

    for (int kv0 = 0; kv0 < S; kv0 += 64) {
        __syncthreads();  // previous PV reads of sK/sV done before overwrite
        {
            const float4* srcK = (const float4*)(gk + base + (size_t)kv0 * 64);
            const float4* srcV = (const float4*)(gv + base + (size_t)kv0 * 64);
            #pragma unroll
            for (int i = tid; i < 1024; i += 128) {
                float4 xk = srcK[i];
                float4 xv = srcV[i];
                float4 yk, yv;
                yk.x = __uint_as_float(f2tf(xk.x));
                yk.y = __uint_as_float(f2tf(xk.y));
                yk.z = __uint_as_float(f2tf(xk.z));
                yk.w = __uint_as_float(f2tf(xk.w));
                yv.x = __uint_as_float(f2tf(xv.x));
                yv.y = __uint_as_float(f2tf(xv.y));
                yv.z = __uint_as_float(f2tf(xv.z));
                yv.w = __uint_as_float(f2tf(xv.w));
                const int off = (i >> 4) * STRIDE + ((i & 15) << 2);
                *(float4*)(sK + off) = yk;
                *(float4*)(sV + off) = yv;
            }
            if (tid < 64) sPad[tid] = gpad[(size_t)b * S + kv0 + tid];
        }
        __syncthreads();

        // ---- S = Q @ K^T ----
        float c[8][4];
        #pragma unroll
        for (int n = 0; n < 8; n++) {
            c[n][0] = c[n][1] = c[n][2] = c[n][3] = 0.f;
            #pragma unroll
            for (int kt = 0; kt < 8; kt++) {
                uint32_t b0 = __float_as_uint(sK[(n * 8 + g) * STRIDE + kt * 8 + t]);
                uint32_t b1 = __float_as_uint(sK[(n * 8 + g) * STRIDE + kt * 8 + t + 4]);
                mma8(c[n], qa[kt], b0, b1);
            }
        }

        // ---- mask + scale ----
        #pragma unroll
        for (int n = 0; n < 8; n++) {
            const int col0 = kv0 + n * 8 + 2 * t;
            const int col1 = col0 + 1;
            bool m00, m01, m10, m11;
            if (mode == 1) {          // lm: causal
                m00 = qr0 >= col0; m01 = qr0 >= col1;
                m10 = qr1 >= col0; m11 = qr1 >= col1;
            } else if (mode == 2) {   // mmu: causal | kv <= 579
                const bool c0c = col0 <= 579, c1c = col1 <= 579;
                m00 = (qr0 >= col0) || c0c; m01 = (qr0 >= col1) || c1c;
                m10 = (qr1 >= col0) || c0c; m11 = (qr1 >= col1) || c1c;
            } else {                  // t2i: eye ^ ((~pad & causal) | full)
                const bool pad0 = col0 < sPad[n * 8 + 2 * t];
                const bool pad1 = col1 < sPad[n * 8 + 2 * t + 1];
                const bool f00 = (col0 < fe0) && (col0 >= fs0);
                const bool f01 = (col1 < fe0) && (col1 >= fs0);
                const bool f10 = (col0 < fe1) && (col0 >= fs1);
                const bool f11 = (col1 < fe1) && (col1 >= fs1);
                m00 = (qr0 == col0) != ((!pad0 && (qr0 >= col0)) || f00);
                m01 = (qr0 == col1) != ((!pad1 && (qr0 >= col1)) || f01);
                m10 = (qr1 == col0) != ((!pad0 && (qr1 >= col0)) || f10);
                m11 = (qr1 == col1) != ((!pad1 && (qr1 >= col1)) || f11);
            }
            c[n][0] = m00 ? c[n][0] * scale : -1e30f;
            c[n][1] = m01 ? c[n][1] * scale : -1e30f;
            c[n][2] = m10 ? c[n][2] * scale : -1e30f;
            c[n][3] = m11 ? c[n][3] * scale : -1e30f;
        }

        // ---- online softmax (quad owns two rows) ----
        float tm0 = -1e30f, tm1 = -1e30f;
        #pragma unroll
        for (int n = 0; n < 8; n++) {
            tm0 = fmaxf(tm0, fmaxf(c[n][0], c[n][1]));
            tm1 = fmaxf(tm1, fmaxf(c[n][2], c[n][3]));
        }
        tm0 = fmaxf(tm0, __shfl_xor_sync(0xffffffffu, tm0, 1));
        tm0 = fmaxf(tm0, __shfl_xor_sync(0xffffffffu, tm0, 2));
        tm1 = fmaxf(tm1, __shfl_xor_sync(0xffffffffu, tm1, 1));
        tm1 = fmaxf(tm1, __shfl_xor_sync(0xffffffffu, tm1, 2));
        const float mn0 = fmaxf(m0, tm0), mn1 = fmaxf(m1, tm1);
        const float al0 = __expf(m0 - mn0), al1 = __expf(m1 - mn1);
        float s0 = 0.f, s1 = 0.f;
        #pragma unroll
        for (int n = 0; n < 8; n++) {
            c[n][0] = __expf(c[n][0] - mn0);
            c[n][1] = __expf(c[n][1] - mn0);
            c[n][2] = __expf(c[n][2] - mn1);
            c[n][3] = __expf(c[n][3] - mn1);
            s0 += c[n][0] + c[n][1];
            s1 += c[n][2] + c[n][3];
        }
        s0 += __shfl_xor_sync(0xffffffffu, s0, 1);
        s0 += __shfl_xor_sync(0xffffffffu, s0, 2);
        s1 += __shfl_xor_sync(0xffffffffu, s1, 1);
        s1 += __shfl_xor_sync(0xffffffffu, s1, 2);
        l0 = l0 * al0 + s0;
        l1 = l1 * al1 + s1;
        m0 = mn0; m1 = mn1;
        #pragma unroll
        for (int n = 0; n < 8; n++) {
            o[n][0] *= al0; o[n][1] *= al0;
            o[n][2] *= al1; o[n][3] *= al1;
        }

        // ---- P -> smem (C-frag layout -> A-frag layout), per-warp private rows ----
        #pragma unroll
        for (int n = 0; n < 8; n++) {
            float2 w0, w1;
            w0.x = __uint_as_float(f2tf(c[n][0]));
            w0.y = __uint_as_float(f2tf(c[n][1]));
            w1.x = __uint_as_float(f2tf(c[n][2]));
            w1.y = __uint_as_float(f2tf(c[n][3]));
            *(float2*)(sP + pr0       * STRIDE + n * 8 + 2 * t) = w0;
            *(float2*)(sP + (pr0 + 8) * STRIDE + n * 8 + 2 * t) = w1;
        }
        __syncwarp();

        // ---- O += P @ V ----
        #pragma unroll
        for (int kt = 0; kt < 8; kt++) {
            uint32_t pa[4];
            pa[0] = __float_as_uint(sP[pr0       * STRIDE + kt * 8 + t]);
            pa[1] = __float_as_uint(sP[(pr0 + 8) * STRIDE + kt * 8 + t]);
            pa[2] = __float_as_uint(sP[pr0       * STRIDE + kt * 8 + t + 4]);
            pa[3] = __float_as_uint(sP[(pr0 + 8) * STRIDE + kt * 8 + t + 4]);
            #pragma unroll
            for (int n = 0; n < 8; n++) {
                uint32_t b0 = __float_as_uint(sV[(kt * 8 + t)     * STRIDE + n * 8 + g]);
                uint32_t b1 = __float_as_uint(sV[(kt * 8 + t + 4) * STRIDE + n * 8 + g]);
                mma8(o[n], pa, b0, b1);
            }
        }
    }

    // ---- epilogue ----
    const float inv0 = 1.f / l0, inv1 = 1.f / l1;
    float* orow0 = gout + base + (size_t)qr0 * 64;
    float* orow1 = gout + base + (size_t)qr1 * 64;
    #pragma unroll
    for (int n = 0; n < 8; n++) {
        float2 w0 = make_float2(o[n][0] * inv0, o[n][1] * inv0);
        float2 w1 = make_float2(o[n][2] * inv1, o[n][3] * inv1);
        *(float2*)(orow0 + n * 8 + 2 * t) = w0;
        *(float2*)(orow1 + n * 8 + 2 * t) = w1;
    }
}

extern "C" void kernel_launch(void* const* d_in, const int* in_sizes, int n_in,
                              void* d_out, int out_size)
{
    const float* q   = (const float*)d_in[0];
    const float* k   = (const float*)d_in[1];
    const float* v   = (const float*)d_in[2];
    const int* pad   = (const int*)d_in[3];
    const int* fs    = (const int*)d_in[4];
    const int* fe    = (const int*)d_in[5];
    const int* bt2i  = (const int*)d_in[6];
    const int* blm   = (const int*)d_in[7];
    float* out = (float*)d_out;

    const int S = in_sizes[4];                       // full_starts: [S]
    const int B = in_sizes[3] / S;                   // pad_ends: [B,S]
    const int H = (int)((long long)in_sizes[0] / ((long long)B * S * 64));

    const size_t smem = (size_t)3 * 64 * STRIDE * sizeof(float) + 64 * sizeof(int);
    cudaFuncSetAttribute(omni_attn_kernel,
                         cudaFuncAttributeMaxDynamicSharedMemorySize, (int)smem);

    dim3 grid(S / 64, B * H);
    omni_attn_kernel<<<grid, 128, smem>>>(q, k, v, pad, fs, fe, bt2i, blm, out, H, S);
}

// round 2
// speedup vs baseline: 1.7367x; 1.7367x over previous
#include <cuda_runtime.h>
#include <cstdint>

// OmniAttention flash-forward, tf32 mma.sync, Q_TILE=128/CTA (32 q-rows per warp),
// KV_TILE=64, swizzled V, data-driven kv-range skipping + fast unmasked path.

#define STRIDE 68  // padded smem row stride (words) for sK / sQP

__device__ __forceinline__ uint32_t f2tf(float x) {
    uint32_t r;
    asm("cvt.rna.tf32.f32 %0, %1;" : "=r"(r) : "f"(x));
    return r;
}

__device__ __forceinline__ void mma8(float* c, const uint32_t* a, uint32_t b0, uint32_t b1) {
    asm volatile(
        "mma.sync.aligned.m16n8k8.row.col.f32.tf32.tf32.f32 "
        "{%0,%1,%2,%3}, {%4,%5,%6,%7}, {%8,%9}, {%0,%1,%2,%3};\n"
        : "+f"(c[0]), "+f"(c[1]), "+f"(c[2]), "+f"(c[3])
        : "r"(a[0]), "r"(a[1]), "r"(a[2]), "r"(a[3]), "r"(b0), "r"(b1));
}

__global__ void __launch_bounds__(128)
omni_attn_kernel(const float* __restrict__ gq, const float* __restrict__ gk,
                 const float* __restrict__ gv,
                 const int* __restrict__ gpad, const int* __restrict__ gfs,
                 const int* __restrict__ gfe,
                 const int* __restrict__ p_bt2i, const int* __restrict__ p_blm,
                 float* __restrict__ gout, int H, int S)
{
    extern __shared__ float smem[];
    float* sK  = smem;                    // 64 x STRIDE, padded
    float* sV  = sK + 64 * STRIDE;        // 64 x 64, xor-swizzled
    float* sQP = sV + 64 * 64;            // 128 x STRIDE (Q staging, then per-warp P)
    int*   sPad = (int*)(sQP + 128 * STRIDE);   // 64
    int*   sRed = sPad + 64;                    // 4

    const int tid  = threadIdx.x;
    const int warp = tid >> 5;
    const int lane = tid & 31;
    const int g = lane >> 2;
    const int t = lane & 3;

    const int q0 = blockIdx.x * 128;
    const int bh = blockIdx.y;
    const int b  = bh / H;

    const int bt2i = p_bt2i[0];
    const int blm  = p_blm[0];
    const int mode = (b < bt2i) ? 0 : ((b < bt2i + blm) ? 1 : 2);

    const size_t base = (size_t)bh * S * 64;

    // ---- stage Q tile (128x64) into sQP, tf32-rounded ----
    {
        const float4* src = (const float4*)(gq + base + (size_t)q0 * 64);
        #pragma unroll
        for (int i = tid; i < 2048; i += 128) {
            float4 x = src[i];
            float4 y;
            y.x = __uint_as_float(f2tf(x.x));
            y.y = __uint_as_float(f2tf(x.y));
            y.z = __uint_as_float(f2tf(x.z));
            y.w = __uint_as_float(f2tf(x.w));
            *(float4*)(sQP + (i >> 4) * STRIDE + ((i & 15) << 2)) = y;
        }
    }
    __syncthreads();

    // ---- Q fragments (2 row-tiles of 16) in registers for whole kernel ----
    uint32_t qa[2][8][4];
    #pragma unroll
    for (int rt = 0; rt < 2; rt++) {
        const int r0 = warp * 32 + rt * 16 + g;
        #pragma unroll
        for (int kt = 0; kt < 8; kt++) {
            qa[rt][kt][0] = __float_as_uint(sQP[r0       * STRIDE + kt * 8 + t]);
            qa[rt][kt][1] = __float_as_uint(sQP[(r0 + 8) * STRIDE + kt * 8 + t]);
            qa[rt][kt][2] = __float_as_uint(sQP[r0       * STRIDE + kt * 8 + t + 4]);
            qa[rt][kt][3] = __float_as_uint(sQP[(r0 + 8) * STRIDE + kt * 8 + t + 4]);
        }
    }

    int qr[2][2];
    int fs[2][2] = {{0,0},{0,0}}, fe[2][2] = {{0,0},{0,0}};
    #pragma unroll
    for (int rt = 0; rt < 2; rt++) {
        qr[rt][0] = q0 + warp * 32 + rt * 16 + g;
        qr[rt][1] = qr[rt][0] + 8;
        if (mode == 0) {
            fs[rt][0] = gfs[qr[rt][0]]; fe[rt][0] = gfe[qr[rt][0]];
            fs[rt][1] = gfs[qr[rt][1]]; fe[rt][1] = gfe[qr[rt][1]];
        }
    }
    const int wmin = q0 + warp * 32;
    const int wmax = wmin + 31;
    const int pe = (mode == 0) ? gpad[(size_t)b * S] : 0;

    // ---- data-driven kv range for this CTA ----
    int kv_end;
    if (mode == 1) {
        kv_end = q0 + 128;
    } else if (mode == 2) {
        kv_end = q0 + 128;
        const int mmu_end = ((576 + 3) / 64 + 1) * 64;   // tiles containing kv <= 579
        if (kv_end < mmu_end) kv_end = mmu_end;
    } else {
        int need = 0;
        #pragma unroll
        for (int rt = 0; rt < 2; rt++)
            #pragma unroll
            for (int h = 0; h < 2; h++) {
                const int qq = qr[rt][h];
                int nd = qq + 1;
                if (fe[rt][h] > nd) nd = fe[rt][h];
                if (qq == pe) nd = S;   // empty row: must count all kv tiles
                if (nd > need) need = nd;
            }
        need = __reduce_max_sync(0xffffffffu, need);
        if (lane == 0) sRed[warp] = need;
        __syncthreads();
        int mx = sRed[0];
        if (sRed[1] > mx) mx = sRed[1];
        if (sRed[2] > mx) mx = sRed[2];
        if (sRed[3] > mx) mx = sRed[3];
        kv_end = (mx + 63) & ~63;
    }
    if (kv_end > S) kv_end = S;

    float o[2][8][4];
    #pragma unroll
    for (int rt = 0; rt < 2; rt++)
        #pragma unroll
        for (int n = 0; n < 8; n++)
            o[rt][n][0] = o[rt][n][1] = o[rt][n][2] = o[rt][n][3] = 0.f;
    float m[2][2] = {{-1e30f,-1e30f},{-1e30f,-1e30f}};
    float l[2][2] = {{0.f,0.f},{0.f,0.f}};

    const float scale = 0.125f;

    for (int kv0 = 0; kv0 < kv_end; kv0 += 64) {
        __syncthreads();
        // ---- cooperative K/V load: K padded, V xor-swizzled ----
        {
            const float4* srcK = (const float4*)(gk + base + (size_t)kv0 * 64);
            const float4* srcV = (const float4*)(gv + base + (size_t)kv0 * 64);
            #pragma unroll
            for (int i = tid; i < 1024; i += 128) {
                float4 xk = srcK[i];
                float4 xv = srcV[i];
                float4 yk, yv;
                yk.x = __uint_as_float(f2tf(xk.x));
                yk.y = __uint_as_float(f2tf(xk.y));
                yk.z = __uint_as_float(f2tf(xk.z));
                yk.w = __uint_as_float(f2tf(xk.w));
                yv.x = __uint_as_float(f2tf(xv.x));
                yv.y = __uint_as_float(f2tf(xv.y));
                yv.z = __uint_as_float(f2tf(xv.z));
                yv.w = __uint_as_float(f2tf(xv.w));
                const int row = i >> 4;
                const int c4  = (i & 15) << 2;
                *(float4*)(sK + row * STRIDE + c4) = yk;
                *(float4*)(sV + row * 64 + (c4 ^ ((row & 7) << 3))) = yv;
            }
            if (mode == 0 && tid < 64) sPad[tid] = gpad[(size_t)b * S + kv0 + tid];
        }
        __syncthreads();

        // ---- per-warp fully-masked-tile skip ----
        bool wskip;
        if (mode == 1) {
            wskip = kv0 > wmax;
        } else if (mode == 2) {
            wskip = (kv0 > wmax) && (kv0 > 579);
        } else {
            bool th_skip = true;
            #pragma unroll
            for (int rt = 0; rt < 2; rt++)
                #pragma unroll
                for (int h = 0; h < 2; h++) {
                    const int r = qr[rt][h];
                    const bool rs = (kv0 > r) &&
                                    (kv0 >= fe[rt][h] || kv0 + 63 < fs[rt][h]) &&
                                    (r != pe);
                    th_skip = th_skip && rs;
                }
            wskip = __all_sync(0xffffffffu, th_skip);
        }
        if (wskip) continue;   // syncthreads at loop top keeps everyone aligned

        // ---- unmasked-tile fast path test ----
        bool nomask;
        if (mode == 1) {
            nomask = (kv0 + 63 <= wmin);
        } else if (mode == 2) {
            nomask = (kv0 + 63 <= 579) || (kv0 + 63 <= wmin);
        } else {
            bool th_nm = true;
            #pragma unroll
            for (int rt = 0; rt < 2; rt++)
                #pragma unroll
                for (int h = 0; h < 2; h++) {
                    const int r = qr[rt][h];
                    const bool full_cov = (fs[rt][h] <= kv0) && (kv0 + 63 < fe[rt][h]) &&
                                          (r < kv0 || r > kv0 + 63);
                    const bool caus_cov = (kv0 >= pe) && (kv0 + 63 < r);
                    th_nm = th_nm && (full_cov || caus_cov);
                }
            nomask = __all_sync(0xffffffffu, th_nm);
        }

        // ---- S = Q @ K^T for both row-tiles (B-frags loaded once) ----
        float c[2][8][4];
        #pragma unroll
        for (int n = 0; n < 8; n++) {
            c[0][n][0] = c[0][n][1] = c[0][n][2] = c[0][n][3] = 0.f;
            c[1][n][0] = c[1][n][1] = c[1][n][2] = c[1][n][3] = 0.f;
            #pragma unroll
            for (int kt = 0; kt < 8; kt++) {
                const uint32_t b0 = __float_as_uint(sK[(n * 8 + g) * STRIDE + kt * 8 + t]);
                const uint32_t b1 = __float_as_uint(sK[(n * 8 + g) * STRIDE + kt * 8 + t + 4]);
                mma8(c[0][n], qa[0][kt], b0, b1);
                mma8(c[1][n], qa[1][kt], b0, b1);
            }
        }

        // ---- mask + scale + online softmax + P store, per row-tile ----
        #pragma unroll
        for (int rt = 0; rt < 2; rt++) {
            const int r0 = qr[rt][0], r1 = qr[rt][1];
            if (nomask) {
                #pragma unroll
                for (int n = 0; n < 8; n++) {
                    c[rt][n][0] *= scale; c[rt][n][1] *= scale;
                    c[rt][n][2] *= scale; c[rt][n][3] *= scale;
                }
            } else {
                #pragma unroll
                for (int n = 0; n < 8; n++) {
                    const int col0 = kv0 + n * 8 + 2 * t;
                    const int col1 = col0 + 1;
                    bool m00, m01, m10, m11;
                    if (mode == 1) {
                        m00 = r0 >= col0; m01 = r0 >= col1;
                        m10 = r1 >= col0; m11 = r1 >= col1;
                    } else if (mode == 2) {
                        const bool c0c = col0 <= 579, c1c = col1 <= 579;
                        m00 = (r0 >= col0) || c0c; m01 = (r0 >= col1) || c1c;
                        m10 = (r1 >= col0) || c0c; m11 = (r1 >= col1) || c1c;
                    } else {
                        const bool pad0 = col0 < sPad[n * 8 + 2 * t];
                        const bool pad1 = col1 < sPad[n * 8 + 2 * t + 1];
                        const bool f00 = (col0 < fe[rt][0]) && (col0 >= fs[rt][0]);
                        const bool f01 = (col1 < fe[rt][0]) && (col1 >= fs[rt][0]);
                        const bool f10 = (col0 < fe[rt][1]) && (col0 >= fs[rt][1]);
                        const bool f11 = (col1 < fe[rt][1]) && (col1 >= fs[rt][1]);
                        m00 = (r0 == col0) != ((!pad0 && (r0 >= col0)) || f00);
                        m01 = (r0 == col1) != ((!pad1 && (r0 >= col1)) || f01);
                        m10 = (r1 == col0) != ((!pad0 && (r1 >= col0)) || f10);
                        m11 = (r1 == col1) != ((!pad1 && (r1 >= col1)) || f11);
                    }
                    c[rt][n][0] = m00 ? c[rt][n][0] * scale : -1e30f;
                    c[rt][n][1] = m01 ? c[rt][n][1] * scale : -1e30f;
                    c[rt][n][2] = m10 ? c[rt][n][2] * scale : -1e30f;
                    c[rt][n][3] = m11 ? c[rt][n][3] * scale : -1e30f;
                }
            }

            float tm0 = -1e30f, tm1 = -1e30f;
            #pragma unroll
            for (int n = 0; n < 8; n++) {
                tm0 = fmaxf(tm0, fmaxf(c[rt][n][0], c[rt][n][1]));
                tm1 = fmaxf(tm1, fmaxf(c[rt][n][2], c[rt][n][3]));
            }
            tm0 = fmaxf(tm0, __shfl_xor_sync(0xffffffffu, tm0, 1));
            tm0 = fmaxf(tm0, __shfl_xor_sync(0xffffffffu, tm0, 2));
            tm1 = fmaxf(tm1, __shfl_xor_sync(0xffffffffu, tm1, 1));
            tm1 = fmaxf(tm1, __shfl_xor_sync(0xffffffffu, tm1, 2));
            const float mn0 = fmaxf(m[rt][0], tm0), mn1 = fmaxf(m[rt][1], tm1);
            const float al0 = __expf(m[rt][0] - mn0), al1 = __expf(m[rt][1] - mn1);
            float s0 = 0.f, s1 = 0.f;
            #pragma unroll
            for (int n = 0; n < 8; n++) {
                c[rt][n][0] = __expf(c[rt][n][0] - mn0);
                c[rt][n][1] = __expf(c[rt][n][1] - mn0);
                c[rt][n][2] = __expf(c[rt][n][2] - mn1);
                c[rt][n][3] = __expf(c[rt][n][3] - mn1);
                s0 += c[rt][n][0] + c[rt][n][1];
                s1 += c[rt][n][2] + c[rt][n][3];
            }
            s0 += __shfl_xor_sync(0xffffffffu, s0, 1);
            s0 += __shfl_xor_sync(0xffffffffu, s0, 2);
            s1 += __shfl_xor_sync(0xffffffffu, s1, 1);
            s1 += __shfl_xor_sync(0xffffffffu, s1, 2);
            l[rt][0] = l[rt][0] * al0 + s0;
            l[rt][1] = l[rt][1] * al1 + s1;
            m[rt][0] = mn0; m[rt][1] = mn1;
            #pragma unroll
            for (int n = 0; n < 8; n++) {
                o[rt][n][0] *= al0; o[rt][n][1] *= al0;
                o[rt][n][2] *= al1; o[rt][n][3] *= al1;
            }

            // P -> per-warp smem rows (C-frag layout -> A-frag layout)
            const int pr0 = warp * 32 + rt * 16 + g;
            #pragma unroll
            for (int n = 0; n < 8; n++) {
                float2 w0, w1;
                w0.x = __uint_as_float(f2tf(c[rt][n][0]));
                w0.y = __uint_as_float(f2tf(c[rt][n][1]));
                w1.x = __uint_as_float(f2tf(c[rt][n][2]));
                w1.y = __uint_as_float(f2tf(c[rt][n][3]));
                *(float2*)(sQP + pr0       * STRIDE + n * 8 + 2 * t) = w0;
                *(float2*)(sQP + (pr0 + 8) * STRIDE + n * 8 + 2 * t) = w1;
            }
        }
        __syncwarp();

        // ---- O += P @ V (V B-frags loaded once, serve both row-tiles) ----
        const int pbase0 = (warp * 32 + g) * STRIDE;
        #pragma unroll
        for (int kt = 0; kt < 8; kt++) {
            uint32_t pa0[4], pa1[4];
            pa0[0] = __float_as_uint(sQP[pbase0                + kt * 8 + t]);
            pa0[1] = __float_as_uint(sQP[pbase0 +  8 * STRIDE  + kt * 8 + t]);
            pa0[2] = __float_as_uint(sQP[pbase0                + kt * 8 + t + 4]);
            pa0[3] = __float_as_uint(sQP[pbase0 +  8 * STRIDE  + kt * 8 + t + 4]);
            pa1[0] = __float_as_uint(sQP[pbase0 + 16 * STRIDE  + kt * 8 + t]);
            pa1[1] = __float_as_uint(sQP[pbase0 + 24 * STRIDE  + kt * 8 + t]);
            pa1[2] = __float_as_uint(sQP[pbase0 + 16 * STRIDE  + kt * 8 + t + 4]);
            pa1[3] = __float_as_uint(sQP[pbase0 + 24 * STRIDE  + kt * 8 + t + 4]);
            const int vr0 = (8 * kt + t) * 64 + g;
            const int vr1 = (8 * kt + t + 4) * 64 + g;
            #pragma unroll
            for (int n = 0; n < 8; n++) {
                const uint32_t b0 = __float_as_uint(sV[vr0 + 8 * (n ^ t)]);
                const uint32_t b1 = __float_as_uint(sV[vr1 + 8 * ((n ^ t) ^ 4)]);
                mma8(o[0][n], pa0, b0, b1);
                mma8(o[1][n], pa1, b0, b1);
            }
        }
    }

    // ---- epilogue ----
    #pragma unroll
    for (int rt = 0; rt < 2; rt++) {
        const float inv0 = 1.f / l[rt][0], inv1 = 1.f / l[rt][1];
        float* orow0 = gout + base + (size_t)qr[rt][0] * 64;
        float* orow1 = gout + base + (size_t)qr[rt][1] * 64;
        #pragma unroll
        for (int n = 0; n < 8; n++) {
            float2 w0 = make_float2(o[rt][n][0] * inv0, o[rt][n][1] * inv0);
            float2 w1 = make_float2(o[rt][n][2] * inv1, o[rt][n][3] * inv1);
            *(float2*)(orow0 + n * 8 + 2 * t) = w0;
            *(float2*)(orow1 + n * 8 + 2 * t) = w1;
        }
    }
}

extern "C" void kernel_launch(void* const* d_in, const int* in_sizes, int n_in,
                              void* d_out, int out_size)
{
    const float* q   = (const float*)d_in[0];
    const float* k   = (const float*)d_in[1];
    const float* v   = (const float*)d_in[2];
    const int* pad   = (const int*)d_in[3];
    const int* fs    = (const int*)d_in[4];
    const int* fe    = (const int*)d_in[5];
    const int* bt2i  = (const int*)d_in[6];
    const int* blm   = (const int*)d_in[7];
    float* out = (float*)d_out;

    const int S = in_sizes[4];
    const int B = in_sizes[3] / S;
    const int H = (int)((long long)in_sizes[0] / ((long long)B * S * 64));

    const size_t smem = (size_t)(64 * STRIDE + 64 * 64 + 128 * STRIDE) * sizeof(float)
                      + 68 * sizeof(int);
    cudaFuncSetAttribute(omni_attn_kernel,
                         cudaFuncAttributeMaxDynamicSharedMemorySize, (int)smem);

    dim3 grid(S / 128, B * H);
    omni_attn_kernel<<<grid, 128, smem>>>(q, k, v, pad, fs, fe, bt2i, blm, out, H, S);
}

// round 3
// speedup vs baseline: 1.9443x; 1.1196x over previous
#include <cuda_runtime.h>
#include <cstdint>

// OmniAttention flash-forward, tf32 mma.sync, Q_TILE=128/CTA (32 q-rows/warp),
// KV_TILE=64, cp.async double-buffered K/V (raw fp32, tensor-core truncation),
// swizzled V, data-driven kv-range skipping + unmasked fast path.

#define STRIDE 68  // padded smem row stride (words) for sK / sQP

__device__ __forceinline__ uint32_t f2tf(float x) {
    uint32_t r;
    asm("cvt.rna.tf32.f32 %0, %1;" : "=r"(r) : "f"(x));
    return r;
}

__device__ __forceinline__ void cpa16(void* dst, const void* src) {
    uint32_t d = (uint32_t)__cvta_generic_to_shared(dst);
    asm volatile("cp.async.cg.shared.global [%0], [%1], 16;" :: "r"(d), "l"(src));
}
__device__ __forceinline__ void cpa4(void* dst, const void* src) {
    uint32_t d = (uint32_t)__cvta_generic_to_shared(dst);
    asm volatile("cp.async.ca.shared.global [%0], [%1], 4;" :: "r"(d), "l"(src));
}

__device__ __forceinline__ void mma8(float* c, const uint32_t* a, uint32_t b0, uint32_t b1) {
    asm volatile(
        "mma.sync.aligned.m16n8k8.row.col.f32.tf32.tf32.f32 "
        "{%0,%1,%2,%3}, {%4,%5,%6,%7}, {%8,%9}, {%0,%1,%2,%3};\n"
        : "+f"(c[0]), "+f"(c[1]), "+f"(c[2]), "+f"(c[3])
        : "r"(a[0]), "r"(a[1]), "r"(a[2]), "r"(a[3]), "r"(b0), "r"(b1));
}

__global__ void __launch_bounds__(128)
omni_attn_kernel(const float* __restrict__ gq, const float* __restrict__ gk,
                 const float* __restrict__ gv,
                 const int* __restrict__ gpad, const int* __restrict__ gfs,
                 const int* __restrict__ gfe,
                 const int* __restrict__ p_bt2i, const int* __restrict__ p_blm,
                 float* __restrict__ gout, int H, int S)
{
    extern __shared__ float smem[];
    float* sK  = smem;                     // 2 stages x 64 x STRIDE
    float* sV  = sK + 2 * 64 * STRIDE;     // 2 stages x 64 x 64 (xor swizzled)
    float* sQP = sV + 2 * 64 * 64;         // 128 x STRIDE (Q staging, then per-warp P)
    int*   sPad = (int*)(sQP + 128 * STRIDE);  // 2 stages x 64
    int*   sRed = sPad + 128;                  // 4

    const int tid  = threadIdx.x;
    const int warp = tid >> 5;
    const int lane = tid & 31;
    const int g = lane >> 2;
    const int t = lane & 3;

    const int q0 = blockIdx.x * 128;
    const int bh = blockIdx.y;
    const int b  = bh / H;

    const int bt2i = p_bt2i[0];
    const int blm  = p_blm[0];
    const int mode = (b < bt2i) ? 0 : ((b < bt2i + blm) ? 1 : 2);

    const size_t base = (size_t)bh * S * 64;

    // ---- issue cp.async for kv tile 0 immediately (overlaps Q staging) ----
    {
        const float4* srcK = (const float4*)(gk + base);
        const float4* srcV = (const float4*)(gv + base);
        #pragma unroll
        for (int j = 0; j < 8; j++) {
            const int i = tid + j * 128;
            const int row = i >> 4, c4 = (i & 15) << 2;
            cpa16(sK + row * STRIDE + c4, srcK + i);
            cpa16(sV + row * 64 + (c4 ^ ((row & 7) << 3)), srcV + i);
        }
        if (mode == 0 && tid < 64) cpa4(sPad + tid, gpad + (size_t)b * S + tid);
        asm volatile("cp.async.commit_group;");
    }

    // ---- stage Q tile (128x64) into sQP, tf32-rounded ----
    {
        const float4* src = (const float4*)(gq + base + (size_t)q0 * 64);
        #pragma unroll
        for (int i = tid; i < 2048; i += 128) {
            float4 x = src[i];
            float4 y;
            y.x = __uint_as_float(f2tf(x.x));
            y.y = __uint_as_float(f2tf(x.y));
            y.z = __uint_as_float(f2tf(x.z));
            y.w = __uint_as_float(f2tf(x.w));
            *(float4*)(sQP + (i >> 4) * STRIDE + ((i & 15) << 2)) = y;
        }
    }

    int qr[2][2];
    int fs[2][2] = {{0,0},{0,0}}, fe[2][2] = {{0,0},{0,0}};
    #pragma unroll
    for (int rt = 0; rt < 2; rt++) {
        qr[rt][0] = q0 + warp * 32 + rt * 16 + g;
        qr[rt][1] = qr[rt][0] + 8;
        if (mode == 0) {
            fs[rt][0] = gfs[qr[rt][0]]; fe[rt][0] = gfe[qr[rt][0]];
            fs[rt][1] = gfs[qr[rt][1]]; fe[rt][1] = gfe[qr[rt][1]];
        }
    }
    const int wmin = q0 + warp * 32;
    const int wmax = wmin + 31;
    const int pe = (mode == 0) ? gpad[(size_t)b * S] : 0;

    // ---- data-driven kv range for this CTA ----
    int kv_end;
    if (mode == 1) {
        kv_end = q0 + 128;
    } else if (mode == 2) {
        kv_end = q0 + 128;
        const int mmu_end = ((576 + 3) / 64 + 1) * 64;
        if (kv_end < mmu_end) kv_end = mmu_end;
    } else {
        int need = 0;
        #pragma unroll
        for (int rt = 0; rt < 2; rt++)
            #pragma unroll
            for (int h = 0; h < 2; h++) {
                const int qq = qr[rt][h];
                int nd = qq + 1;
                if (fe[rt][h] > nd) nd = fe[rt][h];
                if (qq == pe) nd = S;   // empty row: count all kv tiles
                if (nd > need) need = nd;
            }
        need = __reduce_max_sync(0xffffffffu, need);
        if (lane == 0) sRed[warp] = need;
        __syncthreads();
        int mx = sRed[0];
        if (sRed[1] > mx) mx = sRed[1];
        if (sRed[2] > mx) mx = sRed[2];
        if (sRed[3] > mx) mx = sRed[3];
        kv_end = (mx + 63) & ~63;
    }
    if (kv_end > S) kv_end = S;
    const int ntiles = kv_end >> 6;

    __syncthreads();   // Q staging visible

    // ---- Q fragments (2 row-tiles of 16) in registers for whole kernel ----
    uint32_t qa[2][8][4];
    #pragma unroll
    for (int rt = 0; rt < 2; rt++) {
        const int r0 = warp * 32 + rt * 16 + g;
        #pragma unroll
        for (int kt = 0; kt < 8; kt++) {
            qa[rt][kt][0] = __float_as_uint(sQP[r0       * STRIDE + kt * 8 + t]);
            qa[rt][kt][1] = __float_as_uint(sQP[(r0 + 8) * STRIDE + kt * 8 + t]);
            qa[rt][kt][2] = __float_as_uint(sQP[r0       * STRIDE + kt * 8 + t + 4]);
            qa[rt][kt][3] = __float_as_uint(sQP[(r0 + 8) * STRIDE + kt * 8 + t + 4]);
        }
    }

    float o[2][8][4];
    #pragma unroll
    for (int rt = 0; rt < 2; rt++)
        #pragma unroll
        for (int n = 0; n < 8; n++)
            o[rt][n][0] = o[rt][n][1] = o[rt][n][2] = o[rt][n][3] = 0.f;
    float m[2][2] = {{-1e30f,-1e30f},{-1e30f,-1e30f}};
    float l[2][2] = {{0.f,0.f},{0.f,0.f}};

    const float scale = 0.125f;

    for (int it = 0; it < ntiles; it++) {
        const int kv0 = it << 6;
        const int stg = it & 1;
        const float* sKs = sK + stg * 64 * STRIDE;
        const float* sVs = sV + stg * 64 * 64;
        const int*   sPs = sPad + stg * 64;

        __syncthreads();   // compute of it-1 done -> stage (it+1)&1 free
        if (it + 1 < ntiles) {
            const int nstg = (it + 1) & 1;
            const int nkv  = kv0 + 64;
            float* dK = sK + nstg * 64 * STRIDE;
            float* dV = sV + nstg * 64 * 64;
            const float4* srcK = (const float4*)(gk + base + (size_t)nkv * 64);
            const float4* srcV = (const float4*)(gv + base + (size_t)nkv * 64);
            #pragma unroll
            for (int j = 0; j < 8; j++) {
                const int i = tid + j * 128;
                const int row = i >> 4, c4 = (i & 15) << 2;
                cpa16(dK + row * STRIDE + c4, srcK + i);
                cpa16(dV + row * 64 + (c4 ^ ((row & 7) << 3)), srcV + i);
            }
            if (mode == 0 && tid < 64)
                cpa4(sPad + nstg * 64 + tid, gpad + (size_t)b * S + nkv + tid);
            asm volatile("cp.async.commit_group;");
            asm volatile("cp.async.wait_group 1;");
        } else {
            asm volatile("cp.async.wait_group 0;");
        }
        __syncthreads();   // tile it visible to all

        // ---- per-warp fully-masked-tile skip ----
        bool wskip;
        if (mode == 1) {
            wskip = kv0 > wmax;
        } else if (mode == 2) {
            wskip = (kv0 > wmax) && (kv0 > 579);
        } else {
            bool th_skip = true;
            #pragma unroll
            for (int rt = 0; rt < 2; rt++)
                #pragma unroll
                for (int h = 0; h < 2; h++) {
                    const int r = qr[rt][h];
                    const bool rs = (kv0 > r) &&
                                    (kv0 >= fe[rt][h] || kv0 + 63 < fs[rt][h]) &&
                                    (r != pe);
                    th_skip = th_skip && rs;
                }
            wskip = __all_sync(0xffffffffu, th_skip);
        }
        if (wskip) continue;

        // ---- unmasked-tile fast path test ----
        bool nomask;
        if (mode == 1) {
            nomask = (kv0 + 63 <= wmin);
        } else if (mode == 2) {
            nomask = (kv0 + 63 <= 579) || (kv0 + 63 <= wmin);
        } else {
            bool th_nm = true;
            #pragma unroll
            for (int rt = 0; rt < 2; rt++)
                #pragma unroll
                for (int h = 0; h < 2; h++) {
                    const int r = qr[rt][h];
                    const bool full_cov = (fs[rt][h] <= kv0) && (kv0 + 63 < fe[rt][h]) &&
                                          (r < kv0 || r > kv0 + 63);
                    const bool caus_cov = (kv0 >= pe) && (kv0 + 63 < r);
                    th_nm = th_nm && (full_cov || caus_cov);
                }
            nomask = __all_sync(0xffffffffu, th_nm);
        }

        // ---- S = Q @ K^T for both row-tiles (B-frags loaded once) ----
        float c[2][8][4];
        #pragma unroll
        for (int n = 0; n < 8; n++) {
            c[0][n][0] = c[0][n][1] = c[0][n][2] = c[0][n][3] = 0.f;
            c[1][n][0] = c[1][n][1] = c[1][n][2] = c[1][n][3] = 0.f;
            #pragma unroll
            for (int kt = 0; kt < 8; kt++) {
                const uint32_t b0 = __float_as_uint(sKs[(n * 8 + g) * STRIDE + kt * 8 + t]);
                const uint32_t b1 = __float_as_uint(sKs[(n * 8 + g) * STRIDE + kt * 8 + t + 4]);
                mma8(c[0][n], qa[0][kt], b0, b1);
                mma8(c[1][n], qa[1][kt], b0, b1);
            }
        }

        // ---- mask + scale + online softmax + P store, per row-tile ----
        #pragma unroll
        for (int rt = 0; rt < 2; rt++) {
            const int r0 = qr[rt][0], r1 = qr[rt][1];
            if (nomask) {
                #pragma unroll
                for (int n = 0; n < 8; n++) {
                    c[rt][n][0] *= scale; c[rt][n][1] *= scale;
                    c[rt][n][2] *= scale; c[rt][n][3] *= scale;
                }
            } else {
                #pragma unroll
                for (int n = 0; n < 8; n++) {
                    const int col0 = kv0 + n * 8 + 2 * t;
                    const int col1 = col0 + 1;
                    bool m00, m01, m10, m11;
                    if (mode == 1) {
                        m00 = r0 >= col0; m01 = r0 >= col1;
                        m10 = r1 >= col0; m11 = r1 >= col1;
                    } else if (mode == 2) {
                        const bool c0c = col0 <= 579, c1c = col1 <= 579;
                        m00 = (r0 >= col0) || c0c; m01 = (r0 >= col1) || c1c;
                        m10 = (r1 >= col0) || c0c; m11 = (r1 >= col1) || c1c;
                    } else {
                        const bool pad0 = col0 < sPs[n * 8 + 2 * t];
                        const bool pad1 = col1 < sPs[n * 8 + 2 * t + 1];
                        const bool f00 = (col0 < fe[rt][0]) && (col0 >= fs[rt][0]);
                        const bool f01 = (col1 < fe[rt][0]) && (col1 >= fs[rt][0]);
                        const bool f10 = (col0 < fe[rt][1]) && (col0 >= fs[rt][1]);
                        const bool f11 = (col1 < fe[rt][1]) && (col1 >= fs[rt][1]);
                        m00 = (r0 == col0) != ((!pad0 && (r0 >= col0)) || f00);
                        m01 = (r0 == col1) != ((!pad1 && (r0 >= col1)) || f01);
                        m10 = (r1 == col0) != ((!pad0 && (r1 >= col0)) || f10);
                        m11 = (r1 == col1) != ((!pad1 && (r1 >= col1)) || f11);
                    }
                    c[rt][n][0] = m00 ? c[rt][n][0] * scale : -1e30f;
                    c[rt][n][1] = m01 ? c[rt][n][1] * scale : -1e30f;
                    c[rt][n][2] = m10 ? c[rt][n][2] * scale : -1e30f;
                    c[rt][n][3] = m11 ? c[rt][n][3] * scale : -1e30f;
                }
            }

            float tm0 = -1e30f, tm1 = -1e30f;
            #pragma unroll
            for (int n = 0; n < 8; n++) {
                tm0 = fmaxf(tm0, fmaxf(c[rt][n][0], c[rt][n][1]));
                tm1 = fmaxf(tm1, fmaxf(c[rt][n][2], c[rt][n][3]));
            }
            tm0 = fmaxf(tm0, __shfl_xor_sync(0xffffffffu, tm0, 1));
            tm0 = fmaxf(tm0, __shfl_xor_sync(0xffffffffu, tm0, 2));
            tm1 = fmaxf(tm1, __shfl_xor_sync(0xffffffffu, tm1, 1));
            tm1 = fmaxf(tm1, __shfl_xor_sync(0xffffffffu, tm1, 2));
            const float mn0 = fmaxf(m[rt][0], tm0), mn1 = fmaxf(m[rt][1], tm1);
            const float al0 = __expf(m[rt][0] - mn0), al1 = __expf(m[rt][1] - mn1);
            float s0 = 0.f, s1 = 0.f;
            #pragma unroll
            for (int n = 0; n < 8; n++) {
                c[rt][n][0] = __expf(c[rt][n][0] - mn0);
                c[rt][n][1] = __expf(c[rt][n][1] - mn0);
                c[rt][n][2] = __expf(c[rt][n][2] - mn1);
                c[rt][n][3] = __expf(c[rt][n][3] - mn1);
                s0 += c[rt][n][0] + c[rt][n][1];
                s1 += c[rt][n][2] + c[rt][n][3];
            }
            s0 += __shfl_xor_sync(0xffffffffu, s0, 1);
            s0 += __shfl_xor_sync(0xffffffffu, s0, 2);
            s1 += __shfl_xor_sync(0xffffffffu, s1, 1);
            s1 += __shfl_xor_sync(0xffffffffu, s1, 2);
            l[rt][0] = l[rt][0] * al0 + s0;
            l[rt][1] = l[rt][1] * al1 + s1;
            m[rt][0] = mn0; m[rt][1] = mn1;
            #pragma unroll
            for (int n = 0; n < 8; n++) {
                o[rt][n][0] *= al0; o[rt][n][1] *= al0;
                o[rt][n][2] *= al1; o[rt][n][3] *= al1;
            }

            // P -> per-warp smem rows (C-frag layout -> A-frag layout)
            const int pr0 = warp * 32 + rt * 16 + g;
            #pragma unroll
            for (int n = 0; n < 8; n++) {
                float2 w0, w1;
                w0.x = __uint_as_float(f2tf(c[rt][n][0]));
                w0.y = __uint_as_float(f2tf(c[rt][n][1]));
                w1.x = __uint_as_float(f2tf(c[rt][n][2]));
                w1.y = __uint_as_float(f2tf(c[rt][n][3]));
                *(float2*)(sQP + pr0       * STRIDE + n * 8 + 2 * t) = w0;
                *(float2*)(sQP + (pr0 + 8) * STRIDE + n * 8 + 2 * t) = w1;
            }
        }
        __syncwarp();

        // ---- O += P @ V (V B-frags loaded once, serve both row-tiles) ----
        const int pbase0 = (warp * 32 + g) * STRIDE;
        #pragma unroll
        for (int kt = 0; kt < 8; kt++) {
            uint32_t pa0[4], pa1[4];
            pa0[0] = __float_as_uint(sQP[pbase0                + kt * 8 + t]);
            pa0[1] = __float_as_uint(sQP[pbase0 +  8 * STRIDE  + kt * 8 + t]);
            pa0[2] = __float_as_uint(sQP[pbase0                + kt * 8 + t + 4]);
            pa0[3] = __float_as_uint(sQP[pbase0 +  8 * STRIDE  + kt * 8 + t + 4]);
            pa1[0] = __float_as_uint(sQP[pbase0 + 16 * STRIDE  + kt * 8 + t]);
            pa1[1] = __float_as_uint(sQP[pbase0 + 24 * STRIDE  + kt * 8 + t]);
            pa1[2] = __float_as_uint(sQP[pbase0 + 16 * STRIDE  + kt * 8 + t + 4]);
            pa1[3] = __float_as_uint(sQP[pbase0 + 24 * STRIDE  + kt * 8 + t + 4]);
            const int vr0 = (8 * kt + t) * 64 + g;
            const int vr1 = (8 * kt + t + 4) * 64 + g;
            #pragma unroll
            for (int n = 0; n < 8; n++) {
                const uint32_t b0 = __float_as_uint(sVs[vr0 + 8 * (n ^ t)]);
                const uint32_t b1 = __float_as_uint(sVs[vr1 + 8 * ((n ^ t) ^ 4)]);
                mma8(o[0][n], pa0, b0, b1);
                mma8(o[1][n], pa1, b0, b1);
            }
        }
    }

    // ---- epilogue ----
    #pragma unroll
    for (int rt = 0; rt < 2; rt++) {
        const float inv0 = 1.f / l[rt][0], inv1 = 1.f / l[rt][1];
        float* orow0 = gout + base + (size_t)qr[rt][0] * 64;
        float* orow1 = gout + base + (size_t)qr[rt][1] * 64;
        #pragma unroll
        for (int n = 0; n < 8; n++) {
            float2 w0 = make_float2(o[rt][n][0] * inv0, o[rt][n][1] * inv0);
            float2 w1 = make_float2(o[rt][n][2] * inv1, o[rt][n][3] * inv1);
            *(float2*)(orow0 + n * 8 + 2 * t) = w0;
            *(float2*)(orow1 + n * 8 + 2 * t) = w1;
        }
    }
}

extern "C" void kernel_launch(void* const* d_in, const int* in_sizes, int n_in,
                              void* d_out, int out_size)
{
    const float* q   = (const float*)d_in[0];
    const float* k   = (const float*)d_in[1];
    const float* v   = (const float*)d_in[2];
    const int* pad   = (const int*)d_in[3];
    const int* fs    = (const int*)d_in[4];
    const int* fe    = (const int*)d_in[5];
    const int* bt2i  = (const int*)d_in[6];
    const int* blm   = (const int*)d_in[7];
    float* out = (float*)d_out;

    const int S = in_sizes[4];
    const int B = in_sizes[3] / S;
    const int H = (int)((long long)in_sizes[0] / ((long long)B * S * 64));

    const size_t smem = (size_t)(2 * 64 * STRIDE + 2 * 64 * 64 + 128 * STRIDE) * sizeof(float)
                      + 132 * sizeof(int);
    cudaFuncSetAttribute(omni_attn_kernel,
                         cudaFuncAttributeMaxDynamicSharedMemorySize, (int)smem);

    dim3 grid(S / 128, B * H);
    omni_attn_kernel<<<grid, 128, smem>>>(q, k, v, pad, fs, fe, bt2i, blm, out, H, S);
}